// round 1
// baseline (speedup 1.0000x reference)
#include <cuda_runtime.h>

// NonMaximaSuppression2d: out = x * (x > max over 3x3 neighborhood excluding
// center), replicate padding. Shape (8,4,2048,2048) fp32 -> 32 images of
// 2048x2048. Pure HBM-bound streaming stencil.
//
// Strategy: each thread owns a 4-wide (float4) column strip and rolls a
// 3-row register window down R rows. Each row is loaded once per thread
// (plus 2 halo rows per strip and 2 halo scalars per row that hit L1/L2).

#define ROWS_PER_THREAD 8
#define TPB 128          // threads per block -> 512 px per block in x

__device__ __forceinline__ void load_row6(const float* __restrict__ row,
                                          int x4, int W, float a[6]) {
    // a[1..4] = v[x4..x4+3]; a[0] = left halo (replicate), a[5] = right halo.
    float4 v = *reinterpret_cast<const float4*>(row + x4);
    a[1] = v.x; a[2] = v.y; a[3] = v.z; a[4] = v.w;
    a[0] = (x4 > 0)       ? __ldg(row + x4 - 1) : v.x;   // replicate: x=-1 -> x=0
    a[5] = (x4 + 4 < W)   ? __ldg(row + x4 + 4) : v.w;   // replicate: x=W -> W-1
}

__global__ void __launch_bounds__(TPB, 8)
nms2d_kernel(const float* __restrict__ x, float* __restrict__ out,
             int H, int W) {
    const int img = blockIdx.z;
    const size_t base = (size_t)img * H * W;
    const float* __restrict__ p = x + base;
    float* __restrict__ q = out + base;

    const int x4 = (blockIdx.x * TPB + threadIdx.x) * 4;
    const int y0 = blockIdx.y * ROWS_PER_THREAD;

    float top[6], mid[6], bot[6];

    // Prime the window. Replicate padding: y=-1 clamps to 0.
    load_row6(p + (size_t)max(y0 - 1, 0) * W, x4, W, top);
    load_row6(p + (size_t)y0 * W,            x4, W, mid);

    #pragma unroll
    for (int r = 0; r < ROWS_PER_THREAD; r++) {
        const int y = y0 + r;
        const int yb = min(y + 1, H - 1);   // replicate: y=H -> H-1
        load_row6(p + (size_t)yb * W, x4, W, bot);

        float4 o;
        #pragma unroll
        for (int i = 0; i < 4; i++) {
            // full horizontal max of top/bot rows (3 taps), mid row excludes center
            float ft = fmaxf(fmaxf(top[i], top[i + 1]), top[i + 2]);
            float fb = fmaxf(fmaxf(bot[i], bot[i + 1]), bot[i + 2]);
            float nm = fmaxf(mid[i], mid[i + 2]);           // mid, no center
            float nbr = fmaxf(fmaxf(ft, fb), nm);
            float c = mid[i + 1];
            float v = (c > nbr) ? c : 0.0f;
            if (i == 0) o.x = v;
            else if (i == 1) o.y = v;
            else if (i == 2) o.z = v;
            else o.w = v;
        }
        *reinterpret_cast<float4*>(q + (size_t)y * W + x4) = o;

        // Rotate window: top <- mid <- bot
        #pragma unroll
        for (int k = 0; k < 6; k++) { top[k] = mid[k]; mid[k] = bot[k]; }
    }
}

extern "C" void kernel_launch(void* const* d_in, const int* in_sizes, int n_in,
                              void* d_out, int out_size) {
    const float* x = (const float*)d_in[0];
    float* out = (float*)d_out;

    const int H = 2048, W = 2048;
    const int n_img = in_sizes[0] / (H * W);   // 8*4 = 32

    dim3 block(TPB, 1, 1);
    dim3 grid(W / (TPB * 4), H / ROWS_PER_THREAD, n_img);
    nms2d_kernel<<<grid, block>>>(x, out, H, W);
}

// round 2
// speedup vs baseline: 1.1292x; 1.1292x over previous
#include <cuda_runtime.h>

// NonMaximaSuppression2d: out = x * (x > max over 3x3 neighborhood excluding
// center), replicate padding. (8,4,2048,2048) fp32. HBM-bound stream.
//
// R2: front-batched row loads (MLP=6 independent LDG.128 per thread) +
// warp-shuffle horizontal halos (scalar halo LDGs only on lanes 0/31).

#define ROWS 4
#define TPB 128          // 128 threads * float4 = 512 px per block in x

__device__ __forceinline__ float max3(float a, float b, float c) {
    return fmaxf(fmaxf(a, b), c);
}

__global__ void __launch_bounds__(TPB)
nms2d_kernel(const float* __restrict__ x, float* __restrict__ out,
             int H, int W) {
    const int img = blockIdx.z;
    const size_t base = (size_t)img * H * W;
    const float* __restrict__ p = x + base;
    float* __restrict__ q = out + base;

    const int lane = threadIdx.x & 31;
    const int x4 = (blockIdx.x * TPB + threadIdx.x) * 4;
    const int y0 = blockIdx.y * ROWS;

    // ---- Front-batch all ROWS+2 row loads (independent -> high MLP) ----
    float4 v[ROWS + 2];
    #pragma unroll
    for (int j = 0; j < ROWS + 2; j++) {
        const int y = min(max(y0 + j - 1, 0), H - 1);   // replicate pad
        v[j] = *reinterpret_cast<const float4*>(p + (size_t)y * W + x4);
    }

    // ---- Horizontal halos via warp shuffle; warp-edge lanes load scalar ----
    float lh[ROWS + 2], rh[ROWS + 2];
    #pragma unroll
    for (int j = 0; j < ROWS + 2; j++) {
        float fl = __shfl_up_sync(0xffffffffu, v[j].w, 1);
        float fr = __shfl_down_sync(0xffffffffu, v[j].x, 1);
        if (lane == 0) {
            const int y = min(max(y0 + j - 1, 0), H - 1);
            fl = (x4 > 0) ? __ldg(p + (size_t)y * W + x4 - 1) : v[j].x;
        }
        if (lane == 31) {
            const int y = min(max(y0 + j - 1, 0), H - 1);
            fr = (x4 + 4 < W) ? __ldg(p + (size_t)y * W + x4 + 4) : v[j].w;
        }
        lh[j] = fl;
        rh[j] = fr;
    }

    // ---- Compute ROWS output rows ----
    #pragma unroll
    for (int r = 0; r < ROWS; r++) {
        const int t = r, m = r + 1, b = r + 2;

        // full 3-tap horizontal maxes of top and bottom rows
        float t0 = max3(lh[t], v[t].x, v[t].y);
        float t1 = max3(v[t].x, v[t].y, v[t].z);
        float t2 = max3(v[t].y, v[t].z, v[t].w);
        float t3 = max3(v[t].z, v[t].w, rh[t]);

        float b0 = max3(lh[b], v[b].x, v[b].y);
        float b1 = max3(v[b].x, v[b].y, v[b].z);
        float b2 = max3(v[b].y, v[b].z, v[b].w);
        float b3 = max3(v[b].z, v[b].w, rh[b]);

        // mid row: exclude center tap
        float n0 = fmaxf(lh[m],  v[m].y);
        float n1 = fmaxf(v[m].x, v[m].z);
        float n2 = fmaxf(v[m].y, v[m].w);
        float n3 = fmaxf(v[m].z, rh[m]);

        float4 o;
        float nb;
        nb = fmaxf(fmaxf(t0, b0), n0); o.x = (v[m].x > nb) ? v[m].x : 0.0f;
        nb = fmaxf(fmaxf(t1, b1), n1); o.y = (v[m].y > nb) ? v[m].y : 0.0f;
        nb = fmaxf(fmaxf(t2, b2), n2); o.z = (v[m].z > nb) ? v[m].z : 0.0f;
        nb = fmaxf(fmaxf(t3, b3), n3); o.w = (v[m].w > nb) ? v[m].w : 0.0f;

        *reinterpret_cast<float4*>(q + (size_t)(y0 + r) * W + x4) = o;
    }
}

extern "C" void kernel_launch(void* const* d_in, const int* in_sizes, int n_in,
                              void* d_out, int out_size) {
    const float* x = (const float*)d_in[0];
    float* out = (float*)d_out;

    const int H = 2048, W = 2048;
    const int n_img = in_sizes[0] / (H * W);   // 32

    dim3 block(TPB, 1, 1);
    dim3 grid(W / (TPB * 4), H / ROWS, n_img);
    nms2d_kernel<<<grid, block>>>(x, out, H, W);
}